// round 10
// baseline (speedup 1.0000x reference)
#include <cuda_runtime.h>
#include <cuda_bf16.h>
#include <cstdint>

#define NB   4096
#define NK   50
#define ND   64
#define NL   3
#define NTILES 1024        // 32x32 tiles of 128x128

// ---------------- scratch (device globals; no allocation allowed) -----------
__device__ __nv_bfloat16 g_Uh[NB * ND];
__device__ __nv_bfloat16 g_Ul[NB * ND];
__device__ __nv_bfloat16 g_Vh[NB * ND];
__device__ __nv_bfloat16 g_Vl[NB * ND];

#define SWZ128(o) ((uint32_t)(o) ^ (((uint32_t)(o) >> 3) & 0x70u))

__device__ __forceinline__ uint32_t smem_u32(const void* p) {
    uint32_t a;
    asm("{ .reg .u64 t; cvta.to.shared.u64 t, %1; cvt.u32.u64 %0, t; }"
        : "=r"(a) : "l"(p));
    return a;
}
__device__ __forceinline__ void cpa16(uint32_t dst, const void* src) {
    asm volatile("cp.async.cg.shared.global [%0], [%1], 16;"
                 :: "r"(dst), "l"(src) : "memory");
}
#define CP_COMMIT() asm volatile("cp.async.commit_group;" ::: "memory")
#define CP_WAIT(n)  asm volatile("cp.async.wait_group %0;" :: "n"(n) : "memory")

__device__ __forceinline__ void ldm_x4(uint32_t* r, uint32_t addr) {
    asm volatile("ldmatrix.sync.aligned.m8n8.x4.shared.b16 {%0,%1,%2,%3}, [%4];"
                 : "=r"(r[0]), "=r"(r[1]), "=r"(r[2]), "=r"(r[3]) : "r"(addr));
}
__device__ __forceinline__ void ldm_x2(uint32_t* r, uint32_t addr) {
    asm volatile("ldmatrix.sync.aligned.m8n8.x2.shared.b16 {%0,%1}, [%2];"
                 : "=r"(r[0]), "=r"(r[1]) : "r"(addr));
}
__device__ __forceinline__ void mma16816(float* d, const uint32_t* a,
                                         const uint32_t* b) {
    asm volatile(
        "mma.sync.aligned.m16n8k16.row.col.f32.bf16.bf16.f32 "
        "{%0,%1,%2,%3}, {%4,%5,%6,%7}, {%8,%9}, {%0,%1,%2,%3};"
        : "+f"(d[0]), "+f"(d[1]), "+f"(d[2]), "+f"(d[3])
        : "r"(a[0]), "r"(a[1]), "r"(a[2]), "r"(a[3]), "r"(b[0]), "r"(b[1]));
}

// ---- packed f32x2 helpers ----
typedef unsigned long long ull;
__device__ __forceinline__ ull dup2(float x) {
    ull r; asm("mov.b64 %0, {%1, %1};" : "=l"(r) : "f"(x)); return r;
}
__device__ __forceinline__ ull pack2(float lo, float hi) {
    ull r; asm("mov.b64 %0, {%1, %2};" : "=l"(r) : "f"(lo), "f"(hi)); return r;
}
__device__ __forceinline__ void unpack2(ull v, float& lo, float& hi) {
    asm("mov.b64 {%0, %1}, %2;" : "=f"(lo), "=f"(hi) : "l"(v));
}
__device__ __forceinline__ ull mul2(ull a, ull b) {
    ull r; asm("mul.rn.f32x2 %0, %1, %2;" : "=l"(r) : "l"(a), "l"(b)); return r;
}
__device__ __forceinline__ ull add2(ull a, ull b) {
    ull r; asm("add.rn.f32x2 %0, %1, %2;" : "=l"(r) : "l"(a), "l"(b)); return r;
}
__device__ __forceinline__ void fma2(ull& d, ull a, ull b) {
    asm("fma.rn.f32x2 %0, %1, %2, %0;" : "+l"(d) : "l"(a), "l"(b));
}

// ---------------------------------------------------------------------------
// Kernel A: gather + weighted neighbor sums (w,w^2,w^3) + 3-layer MLP.
// CTA: 256 threads = 8 warps x 4 rows/warp = 32 rows. Grid 128.
// f32x2 packed math; W smem traffic cut 4x by 4 rows/warp; warp-private MLP.
// ---------------------------------------------------------------------------
#define WPITCH 66
#define GA_SMEM ((NL * ND * WPITCH + NL * ND + 32 * 64 + 32 * 52 + 32 * 52) * 4)

__global__ __launch_bounds__(256)
void gather_mlp(const int* __restrict__ user_ids,
                const int* __restrict__ item_ids,
                const int* __restrict__ nbr,
                const float* __restrict__ mask,
                const float* __restrict__ ut,
                const float* __restrict__ itab,
                const float* __restrict__ Ws,
                const float* __restrict__ bsv)
{
    extern __shared__ float dsm[];
    float* s_W = dsm;                             // [l][in][WPITCH] transposed
    float* s_b = s_W + NL * ND * WPITCH;          // [l][64]
    float* s_x = s_b + NL * ND;                   // [32][64]
    float* s_m = s_x + 32 * 64;                   // [32][52]
    int*   s_n = (int*)(s_m + 32 * 52);           // [32][52]

    const int tid = threadIdx.x;
    const int wid = tid >> 5;        // 0..7
    const int q   = tid & 31;        // lane -> dims {2q, 2q+1}
    const int b0  = blockIdx.x * 32;

    for (int i = tid; i < 32 * NK; i += 256) {
        int rr = i / NK, kk = i - rr * NK;
        int g = (b0 + rr) * NK + kk;
        s_n[rr * 52 + kk] = nbr[g];
        s_m[rr * 52 + kk] = mask[g];
    }
    // stage W transposed: s_W[l][in][out] = Ws[l][out][in]
    for (int i = tid; i < NL * ND * ND; i += 256) {
        int l = i >> 12, rem = i & 4095;
        int o = rem >> 6, in_ = rem & 63;
        s_W[(l * ND + in_) * WPITCH + o] = Ws[i];
    }
    for (int i = tid; i < NL * ND; i += 256)
        s_b[i] = bsv[i];
    __syncthreads();

    const int r0 = wid * 4;                     // first of 4 rows for this warp
    ull x[4], sums[3][4];

#pragma unroll
    for (int j = 0; j < 4; j++) {
        const int b = b0 + r0 + j;
        // item gather -> bf16 split
        {
            float2 v = *(const float2*)&itab[(long)item_ids[b] * ND + 2 * q];
            __nv_bfloat16 h0 = __float2bfloat16(v.x), h1 = __float2bfloat16(v.y);
            __nv_bfloat162 hh(h0, h1);
            __nv_bfloat162 ll(__float2bfloat16(v.x - __bfloat162float(h0)),
                              __float2bfloat16(v.y - __bfloat162float(h1)));
            int off = b * ND + 2 * q;
            *(__nv_bfloat162*)&g_Vh[off] = hh;
            *(__nv_bfloat162*)&g_Vl[off] = ll;
        }
        {
            float2 uu = *(const float2*)&ut[(long)user_ids[b] * ND + 2 * q];
            x[j] = pack2(uu.x, uu.y);
        }
        // neighbor sums (packed)
        ull a1 = 0, a2 = 0, a3 = 0;
#pragma unroll
        for (int kb = 0; kb < NK; kb += 10) {
            float2 vv[10]; float ww[10];
#pragma unroll
            for (int t = 0; t < 10; t++) {
                int n = s_n[(r0 + j) * 52 + kb + t];
                ww[t] = s_m[(r0 + j) * 52 + kb + t];
                vv[t] = *(const float2*)&ut[(long)n * ND + 2 * q];
            }
#pragma unroll
            for (int t = 0; t < 10; t++) {
                ull wd = dup2(ww[t]);
                ull wv = mul2(wd, pack2(vv[t].x, vv[t].y));
                a1 = add2(a1, wv);
                wv = mul2(wv, wd);
                a2 = add2(a2, wv);
                wv = mul2(wv, wd);
                a3 = add2(a3, wv);
            }
        }
        const ull invd = dup2(1.0f / (float)NK);
        sums[0][j] = mul2(a1, invd);
        sums[1][j] = mul2(a2, invd);
        sums[2][j] = mul2(a3, invd);
    }

    // ---- 3-layer MLP, warp-private (4 rows/warp share W reads) ----
#pragma unroll
    for (int l = 0; l < NL; l++) {
        __syncwarp();
#pragma unroll
        for (int j = 0; j < 4; j++) {
            ull xin = add2(x[j], sums[l][j]);
            float lo, hi; unpack2(xin, lo, hi);
            s_x[(r0 + j) * 64 + 2 * q]     = lo;
            s_x[(r0 + j) * 64 + 2 * q + 1] = hi;
        }
        __syncwarp();

        ull acc[4];
        {
            ull b2 = *(const ull*)&s_b[l * 64 + 2 * q];
            acc[0] = b2; acc[1] = b2; acc[2] = b2; acc[3] = b2;
        }
#pragma unroll
        for (int i4 = 0; i4 < 16; i4++) {
            float4 xv[4];
#pragma unroll
            for (int j = 0; j < 4; j++)
                xv[j] = *(const float4*)&s_x[(r0 + j) * 64 + i4 * 4];
#pragma unroll
            for (int ii = 0; ii < 4; ii++) {
                int i = i4 * 4 + ii;
                ull w2 = *(const ull*)&s_W[(l * ND + i) * WPITCH + 2 * q];
                float xa0 = ii == 0 ? xv[0].x : ii == 1 ? xv[0].y : ii == 2 ? xv[0].z : xv[0].w;
                float xa1 = ii == 0 ? xv[1].x : ii == 1 ? xv[1].y : ii == 2 ? xv[1].z : xv[1].w;
                float xa2 = ii == 0 ? xv[2].x : ii == 1 ? xv[2].y : ii == 2 ? xv[2].z : xv[2].w;
                float xa3 = ii == 0 ? xv[3].x : ii == 1 ? xv[3].y : ii == 2 ? xv[3].z : xv[3].w;
                fma2(acc[0], dup2(xa0), w2);
                fma2(acc[1], dup2(xa1), w2);
                fma2(acc[2], dup2(xa2), w2);
                fma2(acc[3], dup2(xa3), w2);
            }
        }
#pragma unroll
        for (int j = 0; j < 4; j++) {
            float lo, hi; unpack2(acc[j], lo, hi);
            x[j] = pack2(fmaxf(lo, 0.f), fmaxf(hi, 0.f));
        }
    }

    // U bf16 split
#pragma unroll
    for (int j = 0; j < 4; j++) {
        const int b = b0 + r0 + j;
        float lo, hi; unpack2(x[j], lo, hi);
        __nv_bfloat16 h0 = __float2bfloat16(lo), h1 = __float2bfloat16(hi);
        __nv_bfloat162 hh(h0, h1);
        __nv_bfloat162 ll(__float2bfloat16(lo - __bfloat162float(h0)),
                          __float2bfloat16(hi - __bfloat162float(h1)));
        int off = b * ND + 2 * q;
        *(__nv_bfloat162*)&g_Uh[off] = hh;
        *(__nv_bfloat162*)&g_Ul[off] = ll;
    }
}

// ---------------------------------------------------------------------------
// Kernel B: persistent C = U @ V^T, mma.sync bf16 hi/lo split (3 products).
// Grid 148, double-buffered smem tiles (2x64KB) AND double-buffered
// fragments across k-steps (load s+1 while MMA-ing s).
// ---------------------------------------------------------------------------
#define SM_AH 0
#define SM_AL 16384
#define SM_BH 32768
#define SM_BL 49152
#define BUFSZ 65536
#define SM_GEMM (2 * BUFSZ)
#define GGRID 148

__device__ __forceinline__ void stage_tile(uint32_t sbuf, int tile, int tid) {
    const int bM = (tile >> 5) * 128;
    const int bN = (tile & 31) * 128;
    const uint4* Uh4 = (const uint4*)g_Uh;
    const uint4* Ul4 = (const uint4*)g_Ul;
    const uint4* Vh4 = (const uint4*)g_Vh;
    const uint4* Vl4 = (const uint4*)g_Vl;
#pragma unroll
    for (int c = 0; c < 4; c++) {
        int i = tid + c * 256;
        int row = i >> 3, ch = i & 7;
        uint32_t sw = SWZ128(row * 128 + ch * 16);
        cpa16(sbuf + SM_AH + sw, &Uh4[(bM + row) * 8 + ch]);
        cpa16(sbuf + SM_AL + sw, &Ul4[(bM + row) * 8 + ch]);
        cpa16(sbuf + SM_BH + sw, &Vh4[(bN + row) * 8 + ch]);
        cpa16(sbuf + SM_BL + sw, &Vl4[(bN + row) * 8 + ch]);
    }
}

struct Frags { uint32_t ah[4][4], al[4][4], bh[4][2], bl[4][2]; };

__device__ __forceinline__ void load_frags(Frags& f, uint32_t base, int s,
                                           int mw, int nw, int t8, int r8) {
    int arow = r8 + (t8 & 1) * 8;
    int ach  = 2 * s + (t8 >> 1);
#pragma unroll
    for (int mi = 0; mi < 4; mi++) {
        uint32_t sw = SWZ128((mw + mi * 16 + arow) * 128 + ach * 16);
        ldm_x4(f.ah[mi], base + SM_AH + sw);
        ldm_x4(f.al[mi], base + SM_AL + sw);
    }
    int bch = 2 * s + (t8 & 1);
#pragma unroll
    for (int ni = 0; ni < 4; ni++) {
        uint32_t sw = SWZ128((nw + ni * 8 + r8) * 128 + bch * 16);
        ldm_x2(f.bh[ni], base + SM_BH + sw);
        ldm_x2(f.bl[ni], base + SM_BL + sw);
    }
}

__global__ __launch_bounds__(256)
void score_gemm_mma(float* __restrict__ C)
{
    extern __shared__ char smem[];
    const uint32_t sb = smem_u32(smem);
    const int tid = threadIdx.x;
    const int wid = tid >> 5, lid = tid & 31;

    const int mw = (wid & 1) * 64;
    const int nw = (wid >> 1) * 32;
    const int t8 = lid >> 3, r8 = lid & 7;
    const int qr = lid >> 2, qc = (lid & 3) * 2;

    int t = blockIdx.x;
    if (t >= NTILES) return;
    stage_tile(sb, t, tid);
    CP_COMMIT();

    int buf = 0;
    for (; t < NTILES; t += GGRID) {
        const int tn = t + GGRID;
        if (tn < NTILES) {
            stage_tile(sb + (buf ^ 1) * BUFSZ, tn, tid);
            CP_COMMIT();
            CP_WAIT(1);
        } else {
            CP_WAIT(0);
        }
        __syncthreads();

        const uint32_t base = sb + buf * BUFSZ;
        float acc[4][4][4];
#pragma unroll
        for (int mi = 0; mi < 4; mi++)
#pragma unroll
            for (int ni = 0; ni < 4; ni++)
#pragma unroll
                for (int j = 0; j < 4; j++) acc[mi][ni][j] = 0.f;

        Frags f[2];
        load_frags(f[0], base, 0, mw, nw, t8, r8);
#pragma unroll
        for (int s = 0; s < 4; s++) {
            const int cur = s & 1;
            if (s < 3)
                load_frags(f[cur ^ 1], base, s + 1, mw, nw, t8, r8);
#pragma unroll
            for (int mi = 0; mi < 4; mi++)
#pragma unroll
                for (int ni = 0; ni < 4; ni++) {
                    mma16816(acc[mi][ni], f[cur].ah[mi], f[cur].bh[ni]);
                    mma16816(acc[mi][ni], f[cur].ah[mi], f[cur].bl[ni]);
                    mma16816(acc[mi][ni], f[cur].al[mi], f[cur].bh[ni]);
                }
        }

        const long bM = (long)(t >> 5) * 128;
        const long bN = (long)(t & 31) * 128;
#pragma unroll
        for (int mi = 0; mi < 4; mi++) {
            long row0 = bM + mw + mi * 16 + qr;
#pragma unroll
            for (int ni = 0; ni < 4; ni++) {
                long col = bN + nw + ni * 8 + qc;
                *(float2*)&C[row0 * NB + col] =
                    make_float2(acc[mi][ni][0], acc[mi][ni][1]);
                *(float2*)&C[(row0 + 8) * NB + col] =
                    make_float2(acc[mi][ni][2], acc[mi][ni][3]);
            }
        }
        __syncthreads();
        buf ^= 1;
    }
}

// ---------------------------------------------------------------------------
extern "C" void kernel_launch(void* const* d_in, const int* in_sizes, int n_in,
                              void* d_out, int out_size)
{
    const int*   user_ids         = (const int*)  d_in[0];
    const int*   item_ids         = (const int*)  d_in[1];
    const int*   social_neighbors = (const int*)  d_in[2];
    const float* attention_mask   = (const float*)d_in[3];
    const float* user_table       = (const float*)d_in[4];
    const float* item_table       = (const float*)d_in[5];
    const float* Ws               = (const float*)d_in[6];
    const float* bs               = (const float*)d_in[7];
    float* out = (float*)d_out;

    cudaFuncSetAttribute(gather_mlp,
                         cudaFuncAttributeMaxDynamicSharedMemorySize, GA_SMEM);
    cudaFuncSetAttribute(score_gemm_mma,
                         cudaFuncAttributeMaxDynamicSharedMemorySize, SM_GEMM);

    gather_mlp<<<NB / 32, 256, GA_SMEM>>>(user_ids, item_ids, social_neighbors,
                                          attention_mask, user_table,
                                          item_table, Ws, bs);

    score_gemm_mma<<<GGRID, 256, SM_GEMM>>>(out);
}

// round 12
// speedup vs baseline: 1.3220x; 1.3220x over previous
#include <cuda_runtime.h>
#include <cuda_bf16.h>
#include <cstdint>

#define NB   4096
#define NK   50
#define ND   64
#define NL   3
#define NTILES 1024        // 32x32 tiles of 128x128

// ---------------- scratch (device globals; no allocation allowed) -----------
__device__ __nv_bfloat16 g_Uh[NB * ND];
__device__ __nv_bfloat16 g_Ul[NB * ND];
__device__ __nv_bfloat16 g_Vh[NB * ND];
__device__ __nv_bfloat16 g_Vl[NB * ND];

#define SWZ128(o) ((uint32_t)(o) ^ (((uint32_t)(o) >> 3) & 0x70u))

__device__ __forceinline__ uint32_t smem_u32(const void* p) {
    uint32_t a;
    asm("{ .reg .u64 t; cvta.to.shared.u64 t, %1; cvt.u32.u64 %0, t; }"
        : "=r"(a) : "l"(p));
    return a;
}
__device__ __forceinline__ void cpa16(uint32_t dst, const void* src) {
    asm volatile("cp.async.cg.shared.global [%0], [%1], 16;"
                 :: "r"(dst), "l"(src) : "memory");
}
#define CP_COMMIT() asm volatile("cp.async.commit_group;" ::: "memory")
#define CP_WAIT(n)  asm volatile("cp.async.wait_group %0;" :: "n"(n) : "memory")

__device__ __forceinline__ void ldm_x4(uint32_t* r, uint32_t addr) {
    asm volatile("ldmatrix.sync.aligned.m8n8.x4.shared.b16 {%0,%1,%2,%3}, [%4];"
                 : "=r"(r[0]), "=r"(r[1]), "=r"(r[2]), "=r"(r[3]) : "r"(addr));
}
__device__ __forceinline__ void ldm_x2(uint32_t* r, uint32_t addr) {
    asm volatile("ldmatrix.sync.aligned.m8n8.x2.shared.b16 {%0,%1}, [%2];"
                 : "=r"(r[0]), "=r"(r[1]) : "r"(addr));
}
__device__ __forceinline__ void mma16816(float* d, const uint32_t* a,
                                         const uint32_t* b) {
    asm volatile(
        "mma.sync.aligned.m16n8k16.row.col.f32.bf16.bf16.f32 "
        "{%0,%1,%2,%3}, {%4,%5,%6,%7}, {%8,%9}, {%0,%1,%2,%3};"
        : "+f"(d[0]), "+f"(d[1]), "+f"(d[2]), "+f"(d[3])
        : "r"(a[0]), "r"(a[1]), "r"(a[2]), "r"(a[3]), "r"(b[0]), "r"(b[1]));
}

// ---------------------------------------------------------------------------
// Kernel A (R9 proven): gather + weighted sums (w,w^2,w^3) + 3-layer MLP.
// 512 threads = 16 rows x 32 lanes (float2 per lane). Grid 256.
// ---------------------------------------------------------------------------
#define GA_SMEM ((NL * ND * 68 + NL * ND + 16 * 64 + 16 * 64 + 16 * 64) * 4)

__global__ __launch_bounds__(512)
void gather_mlp(const int* __restrict__ user_ids,
                const int* __restrict__ item_ids,
                const int* __restrict__ nbr,
                const float* __restrict__ mask,
                const float* __restrict__ ut,
                const float* __restrict__ itab,
                const float* __restrict__ Ws,
                const float* __restrict__ bsv)
{
    extern __shared__ float dsm[];
    float* s_W = dsm;                        // [l][in][68] transposed, padded
    float* s_b = s_W + NL * ND * 68;         // [l][64]
    float* s_x = s_b + NL * ND;              // [16][64]
    float* s_m = s_x + 16 * 64;              // [16][64] (NK=50 used)
    int*   s_n = (int*)(s_m + 16 * 64);      // [16][64]

    const int tid = threadIdx.x;
    const int r = tid >> 5;          // 0..15 row
    const int q = tid & 31;          // 0..31 lane -> dims {2q, 2q+1}
    const int b0 = blockIdx.x * 16;
    const int b = b0 + r;

    for (int i = tid; i < 16 * NK; i += 512) {
        int rr = i / NK, kk = i - rr * NK;
        int g = (b0 + rr) * NK + kk;
        s_n[rr * 64 + kk] = nbr[g];
        s_m[rr * 64 + kk] = mask[g];
    }
    for (int i = tid; i < NL * ND * ND; i += 512) {
        int l = i >> 12, rem = i & 4095;
        int o = rem >> 6, in_ = rem & 63;
        s_W[(l * ND + in_) * 68 + o] = Ws[i];
    }
    for (int i = tid; i < NL * ND; i += 512)
        s_b[i] = bsv[i];
    __syncthreads();

    // item gather -> bf16 split
    {
        float2 v = *(const float2*)&itab[(long)item_ids[b] * ND + 2 * q];
        __nv_bfloat16 h0 = __float2bfloat16(v.x), h1 = __float2bfloat16(v.y);
        __nv_bfloat162 hh(h0, h1);
        __nv_bfloat162 ll(__float2bfloat16(v.x - __bfloat162float(h0)),
                          __float2bfloat16(v.y - __bfloat162float(h1)));
        int off = b * ND + 2 * q;
        *(__nv_bfloat162*)&g_Vh[off] = hh;
        *(__nv_bfloat162*)&g_Vl[off] = ll;
    }

    float2 u = *(const float2*)&ut[(long)user_ids[b] * ND + 2 * q];

    float a1x=0,a1y=0, a2x=0,a2y=0, a3x=0,a3y=0;
#pragma unroll
    for (int kb = 0; kb < NK; kb += 10) {
        float2 vv[10]; float ww[10];
#pragma unroll
        for (int j = 0; j < 10; j++) {
            int n = s_n[r * 64 + kb + j];
            ww[j] = s_m[r * 64 + kb + j];
            vv[j] = *(const float2*)&ut[(long)n * ND + 2 * q];
        }
#pragma unroll
        for (int j = 0; j < 10; j++) {
            float w = ww[j];
            float tx = w * vv[j].x, ty = w * vv[j].y;
            a1x += tx; a1y += ty;
            tx *= w; ty *= w;
            a2x += tx; a2y += ty;
            tx *= w; ty *= w;
            a3x += tx; a3y += ty;
        }
    }
    const float inv = 1.0f / (float)NK;
    float2 sums[3] = { make_float2(a1x*inv, a1y*inv),
                       make_float2(a2x*inv, a2y*inv),
                       make_float2(a3x*inv, a3y*inv) };

    float2 x = u;
#pragma unroll
    for (int l = 0; l < NL; l++) {
        s_x[r * 64 + 2*q]     = x.x + sums[l].x;
        s_x[r * 64 + 2*q + 1] = x.y + sums[l].y;
        __syncthreads();
        float ax = s_b[l * 64 + 2*q], ay = s_b[l * 64 + 2*q + 1];
#pragma unroll
        for (int i = 0; i < ND; i++) {
            float xi = s_x[r * 64 + i];
            float2 w2 = *(const float2*)&s_W[(l * ND + i) * 68 + 2*q];
            ax = fmaf(xi, w2.x, ax);
            ay = fmaf(xi, w2.y, ay);
        }
        x = make_float2(fmaxf(ax, 0.f), fmaxf(ay, 0.f));
        __syncthreads();
    }

    {
        __nv_bfloat16 h0 = __float2bfloat16(x.x), h1 = __float2bfloat16(x.y);
        __nv_bfloat162 hh(h0, h1);
        __nv_bfloat162 ll(__float2bfloat16(x.x - __bfloat162float(h0)),
                          __float2bfloat16(x.y - __bfloat162float(h1)));
        int off = b * ND + 2 * q;
        *(__nv_bfloat162*)&g_Uh[off] = hh;
        *(__nv_bfloat162*)&g_Ul[off] = ll;
    }
}

// ---------------------------------------------------------------------------
// Kernel B: persistent C = U @ V^T, mma.sync bf16 hi/lo split (3 products).
// Grid 148 persistent, 512 threads = 16 warps (4x4), warp tile 32x32.
// Double-buffered 64KB smem tiles. ~90 regs/thread -> 4 warps/SMSP.
// ---------------------------------------------------------------------------
#define SM_AH 0
#define SM_AL 16384
#define SM_BH 32768
#define SM_BL 49152
#define BUFSZ 65536
#define SM_GEMM (2 * BUFSZ)
#define GGRID 148

__device__ __forceinline__ void stage_tile(uint32_t sbuf, int tile, int tid) {
    const int bM = (tile >> 5) * 128;
    const int bN = (tile & 31) * 128;
    const uint4* Uh4 = (const uint4*)g_Uh;
    const uint4* Ul4 = (const uint4*)g_Ul;
    const uint4* Vh4 = (const uint4*)g_Vh;
    const uint4* Vl4 = (const uint4*)g_Vl;
#pragma unroll
    for (int c = 0; c < 2; c++) {
        int i = tid + c * 512;          // 0..1023
        int row = i >> 3, ch = i & 7;
        uint32_t sw = SWZ128(row * 128 + ch * 16);
        cpa16(sbuf + SM_AH + sw, &Uh4[(bM + row) * 8 + ch]);
        cpa16(sbuf + SM_AL + sw, &Ul4[(bM + row) * 8 + ch]);
        cpa16(sbuf + SM_BH + sw, &Vh4[(bN + row) * 8 + ch]);
        cpa16(sbuf + SM_BL + sw, &Vl4[(bN + row) * 8 + ch]);
    }
}

__global__ __launch_bounds__(512)
void score_gemm_mma(float* __restrict__ C)
{
    extern __shared__ char smem[];
    const uint32_t sb = smem_u32(smem);
    const int tid = threadIdx.x;
    const int wid = tid >> 5, lid = tid & 31;

    const int mw = (wid & 3) * 32;       // 4 m-groups of 32
    const int nw = (wid >> 2) * 32;      // 4 n-groups of 32
    const int t8 = lid >> 3, r8 = lid & 7;
    const int qr = lid >> 2, qc = (lid & 3) * 2;

    int t = blockIdx.x;
    if (t >= NTILES) return;
    stage_tile(sb, t, tid);
    CP_COMMIT();

    int buf = 0;
    for (; t < NTILES; t += GGRID) {
        const int tn = t + GGRID;
        if (tn < NTILES) {
            stage_tile(sb + (buf ^ 1) * BUFSZ, tn, tid);
            CP_COMMIT();
            CP_WAIT(1);
        } else {
            CP_WAIT(0);
        }
        __syncthreads();

        const uint32_t base = sb + buf * BUFSZ;
        float acc[2][4][4];
#pragma unroll
        for (int mi = 0; mi < 2; mi++)
#pragma unroll
            for (int ni = 0; ni < 4; ni++)
#pragma unroll
                for (int j = 0; j < 4; j++) acc[mi][ni][j] = 0.f;

#pragma unroll
        for (int s = 0; s < 4; s++) {    // k-steps of 16
            uint32_t ah[2][4], al[2][4], bh[4][2], bl[4][2];
            {
                int arow = r8 + (t8 & 1) * 8;
                int ach  = 2 * s + (t8 >> 1);
#pragma unroll
                for (int mi = 0; mi < 2; mi++) {
                    uint32_t sw = SWZ128((mw + mi * 16 + arow) * 128 + ach * 16);
                    ldm_x4(ah[mi], base + SM_AH + sw);
                    ldm_x4(al[mi], base + SM_AL + sw);
                }
                int bch = 2 * s + (t8 & 1);
#pragma unroll
                for (int ni = 0; ni < 4; ni++) {
                    uint32_t sw = SWZ128((nw + ni * 8 + r8) * 128 + bch * 16);
                    ldm_x2(bh[ni], base + SM_BH + sw);
                    ldm_x2(bl[ni], base + SM_BL + sw);
                }
            }
#pragma unroll
            for (int mi = 0; mi < 2; mi++)
#pragma unroll
                for (int ni = 0; ni < 4; ni++) {
                    mma16816(acc[mi][ni], ah[mi], bh[ni]);
                    mma16816(acc[mi][ni], ah[mi], bl[ni]);
                    mma16816(acc[mi][ni], al[mi], bh[ni]);
                }
        }

        const long bM = (long)(t >> 5) * 128;
        const long bN = (long)(t & 31) * 128;
#pragma unroll
        for (int mi = 0; mi < 2; mi++) {
            long row0 = bM + mw + mi * 16 + qr;
#pragma unroll
            for (int ni = 0; ni < 4; ni++) {
                long col = bN + nw + ni * 8 + qc;
                *(float2*)&C[row0 * NB + col] =
                    make_float2(acc[mi][ni][0], acc[mi][ni][1]);
                *(float2*)&C[(row0 + 8) * NB + col] =
                    make_float2(acc[mi][ni][2], acc[mi][ni][3]);
            }
        }
        __syncthreads();
        buf ^= 1;
    }
}

// ---------------------------------------------------------------------------
extern "C" void kernel_launch(void* const* d_in, const int* in_sizes, int n_in,
                              void* d_out, int out_size)
{
    const int*   user_ids         = (const int*)  d_in[0];
    const int*   item_ids         = (const int*)  d_in[1];
    const int*   social_neighbors = (const int*)  d_in[2];
    const float* attention_mask   = (const float*)d_in[3];
    const float* user_table       = (const float*)d_in[4];
    const float* item_table       = (const float*)d_in[5];
    const float* Ws               = (const float*)d_in[6];
    const float* bs               = (const float*)d_in[7];
    float* out = (float*)d_out;

    cudaFuncSetAttribute(gather_mlp,
                         cudaFuncAttributeMaxDynamicSharedMemorySize, GA_SMEM);
    cudaFuncSetAttribute(score_gemm_mma,
                         cudaFuncAttributeMaxDynamicSharedMemorySize, SM_GEMM);

    gather_mlp<<<NB / 16, 512, GA_SMEM>>>(user_ids, item_ids, social_neighbors,
                                          attention_mask, user_table,
                                          item_table, Ws, bs);

    score_gemm_mma<<<GGRID, 512, SM_GEMM>>>(out);
}